// round 3
// baseline (speedup 1.0000x reference)
#include <cuda_runtime.h>
#include <cstdint>

// ============================================================================
// Problem constants
// ============================================================================
static constexpr int BB   = 8192;   // batch
static constexpr int IN_  = 2048;   // K
static constexpr int OUT_ = 3072;   // N total
static constexpr int S_   = 8;      // subjects

static constexpr int TM   = 128;    // CTA M tile
static constexpr int TN   = 256;    // CTA N tile
static constexpr int KC   = 32;     // K per chunk
static constexpr int NKC  = IN_ / KC;    // 64
static constexpr int NT_N = OUT_ / TN;   // 12
static constexpr int MAX_TILES = 72;     // >= 8192/128 + 7 pad tiles
static constexpr int NTHREADS = 512;     // 16 warps: 2 (m) x 8 (n), warp tile 64x32
static constexpr int STAGES = 4;

static constexpr int A_BYTES = TM * KC * 4;           // 16384
static constexpr int B_BYTES = KC * TN * 4;           // 32768
static constexpr int STAGE_BYTES = A_BYTES + B_BYTES; // 49152
static constexpr int SMEM_TOTAL  = STAGES * STAGE_BYTES; // 196608

// ============================================================================
// Device globals (scratch)
// ============================================================================
__device__ int g_is64;
__device__ int g_counts[S_];
__device__ int g_cursor[S_];
__device__ int g_pad_off[S_];
__device__ int g_tile_subject[MAX_TILES];
__device__ int g_perm[MAX_TILES * TM];

// ============================================================================
// Helpers
// ============================================================================
#define DI __device__ __forceinline__

DI unsigned smem_u32(const void* p) {
    unsigned a;
    asm("{ .reg .u64 t; cvta.to.shared.u64 t, %1; cvt.u32.u64 %0, t; }" : "=r"(a) : "l"(p));
    return a;
}
// A tile: 128 rows (m) x 128B (k). xor bits[6:4] with row%8
DI unsigned swzA(unsigned o) { return o ^ ((o >> 3) & 0x70u); }
// B tile: 32 rows (k) x 1024B (n). xor bits[6:5] with k%4
DI unsigned swzB(unsigned o) { return o ^ ((o >> 5) & 0x60u); }

DI void cpasync16(unsigned dst, const void* src, int src_sz) {
    asm volatile("cp.async.cg.shared.global [%0], [%1], 16, %2;"
                 :: "r"(dst), "l"(src), "r"(src_sz) : "memory");
}
DI void cp_commit() { asm volatile("cp.async.commit_group;" ::: "memory"); }
template <int N> DI void cp_wait() {
    asm volatile("cp.async.wait_group %0;" :: "n"(N) : "memory");
}
// ld.shared.b32 + round-to-nearest tf32 conversion
DI unsigned lds_tf32(unsigned addr) {
    float v; unsigned u;
    asm volatile("ld.shared.b32 %0, [%1];" : "=f"(v) : "r"(addr));
    asm volatile("cvt.rna.tf32.f32 %0, %1;" : "=r"(u) : "f"(v));
    return u;
}
DI void mma_tf32(float* d, const unsigned* a, const unsigned* b) {
    asm volatile(
        "mma.sync.aligned.m16n8k8.row.col.f32.tf32.tf32.f32 "
        "{%0,%1,%2,%3}, {%4,%5,%6,%7}, {%8,%9}, {%0,%1,%2,%3};"
        : "+f"(d[0]), "+f"(d[1]), "+f"(d[2]), "+f"(d[3])
        : "r"(a[0]), "r"(a[1]), "r"(a[2]), "r"(a[3]), "r"(b[0]), "r"(b[1]));
}

// Read subject id b, robust to int32 vs int64 storage
DI int read_sid(const void* sid, int b) {
    if (g_is64) return (int)((const long long*)sid)[b];
    return ((const int*)sid)[b];
}

// ============================================================================
// Setup kernels
// ============================================================================
// Detect int64 vs int32: inspect first 256 int32 words (in-bounds for both).
// int64 small values => every odd word is 0. int32 values uniform in [0,8)
// have P(all 128 odd words zero) = 8^-128 ~ 0.
__global__ void k_detect(const int* __restrict__ sid_raw) {
    __shared__ int any_nonzero;
    if (threadIdx.x == 0) any_nonzero = 0;
    __syncthreads();
    int j = 2 * threadIdx.x + 1;           // odd words 1,3,...,255
    if (j < 256 && sid_raw[j] != 0) atomicOr(&any_nonzero, 1);
    __syncthreads();
    if (threadIdx.x == 0) g_is64 = (any_nonzero == 0) ? 1 : 0;
}
__global__ void k_init() {
    int t = blockIdx.x * blockDim.x + threadIdx.x;
    if (t < S_) { g_counts[t] = 0; g_cursor[t] = 0; }
    if (t < MAX_TILES) g_tile_subject[t] = -1;
    for (int i = t; i < MAX_TILES * TM; i += gridDim.x * blockDim.x) g_perm[i] = -1;
}
__global__ void k_hist(const void* __restrict__ sid) {
    __shared__ int lc[S_];
    int t = threadIdx.x;
    int b = blockIdx.x * blockDim.x + t;
    if (t < S_) lc[t] = 0;
    __syncthreads();
    int s = read_sid(sid, b) & (S_ - 1);
    atomicAdd(&lc[s], 1);
    __syncthreads();
    if (t < S_ && lc[t] > 0) atomicAdd(&g_counts[t], lc[t]);
}
__global__ void k_plan() {
    int off = 0, tile = 0;
    for (int s = 0; s < S_; s++) {
        g_pad_off[s] = off;
        int nt = (g_counts[s] + TM - 1) / TM;
        for (int t = 0; t < nt; t++) g_tile_subject[tile++] = s;
        off += nt * TM;
    }
}
__global__ void k_scatter(const void* __restrict__ sid) {
    __shared__ int lc[S_], lbase[S_];
    int t = threadIdx.x;
    int b = blockIdx.x * blockDim.x + t;
    if (t < S_) lc[t] = 0;
    __syncthreads();
    int s = read_sid(sid, b) & (S_ - 1);
    int r = atomicAdd(&lc[s], 1);
    __syncthreads();
    if (t < S_) lbase[t] = (lc[t] > 0) ? atomicAdd(&g_cursor[t], lc[t]) : 0;
    __syncthreads();
    g_perm[g_pad_off[s] + lbase[s] + r] = b;
}

// ============================================================================
// Grouped tf32 GEMM via mma.sync.m16n8k8 (sm_80-baseline path)
// CTA: 128(m) x 256(n), K streamed in chunks of 32. 16 warps, warp = 64x32.
// ============================================================================
__global__ void __launch_bounds__(NTHREADS, 1)
k_gemm(const float* __restrict__ x, const float* __restrict__ W,
       const float* __restrict__ bias, float* __restrict__ out) {
    extern __shared__ char smem[];
    const int sub = g_tile_subject[blockIdx.x];
    if (sub < 0) return;

    const int tid  = threadIdx.x;
    const int wid  = tid >> 5;
    const int lane = tid & 31;
    const int q    = lane >> 2;    // 0..7
    const int kk   = lane & 3;     // 0..3
    const int wm   = wid >> 3;     // 0..1
    const int wn   = wid & 7;      // 0..7
    const int m_base = blockIdx.x * TM;
    const int n_base = blockIdx.y * TN;
    const unsigned sb = smem_u32(smem);

    const float* Ws = W + (size_t)sub * IN_ * OUT_;

    // ---- cp.async source/dest precompute ----
    // A: 1024 float4 per chunk; thread handles rows t/8 and t/8+64, f4 = t%8
    const int arow0 = tid >> 3;
    const int af4   = tid & 7;
    int pa0 = g_perm[m_base + arow0];
    int pa1 = g_perm[m_base + arow0 + 64];
    const float* asrc0 = x + (size_t)(pa0 < 0 ? 0 : pa0) * IN_ + af4 * 4;
    const float* asrc1 = x + (size_t)(pa1 < 0 ? 0 : pa1) * IN_ + af4 * 4;
    const int asz0 = (pa0 >= 0) ? 16 : 0;
    const int asz1 = (pa1 >= 0) ? 16 : 0;
    const unsigned adst0 = swzA((unsigned)(arow0 * 128 + af4 * 16));
    const unsigned adst1 = swzA((unsigned)((arow0 + 64) * 128 + af4 * 16));

    // B: 2048 float4 per chunk; thread handles k = t/64 + 8i, nf4 = t%64
    const int bk0  = tid >> 6;       // 0..7
    const int bnf4 = tid & 63;       // 0..63
    const float* bsrc = Ws + (size_t)bk0 * OUT_ + n_base + bnf4 * 4;
    unsigned bdst[4];
#pragma unroll
    for (int i = 0; i < 4; i++)
        bdst[i] = swzB((unsigned)((bk0 + 8 * i) * 1024 + bnf4 * 16));

    // ---- pipeline prologue: chunks 0..2 ----
#pragma unroll
    for (int c = 0; c < STAGES - 1; c++) {
        const unsigned st = sb + (unsigned)(c % STAGES) * STAGE_BYTES;
        cpasync16(st + adst0, asrc0 + c * KC, asz0);
        cpasync16(st + adst1, asrc1 + c * KC, asz1);
        const float* bs = bsrc + (size_t)c * KC * OUT_;
#pragma unroll
        for (int i = 0; i < 4; i++)
            cpasync16(st + A_BYTES + bdst[i], bs + (size_t)(8 * i) * OUT_, 16);
        cp_commit();
    }

    float acc[4][4][4];
#pragma unroll
    for (int i = 0; i < 4; i++)
#pragma unroll
        for (int j = 0; j < 4; j++)
#pragma unroll
            for (int c = 0; c < 4; c++) acc[i][j][c] = 0.f;

    // Per-thread fragment address components (xor terms are per-thread consts)
    const unsigned axor = (unsigned)(q * 16);
    const unsigned bxor = (unsigned)(kk * 32);

    // ---- main loop ----
#pragma unroll 1
    for (int kc = 0; kc < NKC; kc++) {
        cp_wait<STAGES - 2>();
        __syncthreads();
        const unsigned st = sb + (unsigned)(kc % STAGES) * STAGE_BYTES;
        const unsigned aT = st;
        const unsigned bT = st + A_BYTES;

#pragma unroll
        for (int ks = 0; ks < 4; ks++) {
            const int kb = ks * 8 + kk;  // k index for this thread's frags
            unsigned a[4][4], b[4][2];
#pragma unroll
            for (int ma = 0; ma < 4; ma++) {
                const unsigned rb = aT + (unsigned)((wm * 64 + ma * 16 + q) * 128);
                a[ma][0] = lds_tf32(rb +        (((unsigned)(kb * 4))      ^ axor));
                a[ma][1] = lds_tf32(rb + 1024 + (((unsigned)(kb * 4))      ^ axor));
                a[ma][2] = lds_tf32(rb +        (((unsigned)(kb * 4 + 16)) ^ axor));
                a[ma][3] = lds_tf32(rb + 1024 + (((unsigned)(kb * 4 + 16)) ^ axor));
            }
#pragma unroll
            for (int na = 0; na < 4; na++) {
                const unsigned co = (((unsigned)((wn * 32 + na * 8 + q) * 4)) ^ bxor);
                b[na][0] = lds_tf32(bT + (unsigned)(kb * 1024)        + co);
                b[na][1] = lds_tf32(bT + (unsigned)((kb + 4) * 1024)  + co);
            }
#pragma unroll
            for (int ma = 0; ma < 4; ma++)
#pragma unroll
                for (int na = 0; na < 4; na++)
                    mma_tf32(acc[ma][na], a[ma], b[na]);
        }

        // prefetch chunk kc+3 into stage (kc+3)%STAGES
        const int nk = kc + STAGES - 1;
        if (nk < NKC) {
            const unsigned ns = sb + (unsigned)(nk % STAGES) * STAGE_BYTES;
            cpasync16(ns + adst0, asrc0 + nk * KC, asz0);
            cpasync16(ns + adst1, asrc1 + nk * KC, asz1);
            const float* bs = bsrc + (size_t)nk * KC * OUT_;
#pragma unroll
            for (int i = 0; i < 4; i++)
                cpasync16(ns + A_BYTES + bdst[i], bs + (size_t)(8 * i) * OUT_, 16);
        }
        cp_commit();  // always commit so wait_group<N> tracks chunk completion
    }

    // ---- epilogue: direct global stores through permutation ----
    const float* bias_s = bias + (size_t)sub * OUT_;
    float2 bv[4];
#pragma unroll
    for (int na = 0; na < 4; na++) {
        const int col = n_base + wn * 32 + na * 8 + kk * 2;
        bv[na] = *(const float2*)(bias_s + col);
    }
#pragma unroll
    for (int ma = 0; ma < 4; ma++) {
        const int mr = m_base + wm * 64 + ma * 16 + q;
        const int p0 = g_perm[mr];
        const int p1 = g_perm[mr + 8];
        float* o0 = out + (size_t)(p0 < 0 ? 0 : p0) * OUT_;
        float* o1 = out + (size_t)(p1 < 0 ? 0 : p1) * OUT_;
#pragma unroll
        for (int na = 0; na < 4; na++) {
            const int col = n_base + wn * 32 + na * 8 + kk * 2;
            if (p0 >= 0) {
                float2 v = make_float2(acc[ma][na][0] + bv[na].x,
                                       acc[ma][na][1] + bv[na].y);
                *(float2*)(o0 + col) = v;
            }
            if (p1 >= 0) {
                float2 v = make_float2(acc[ma][na][2] + bv[na].x,
                                       acc[ma][na][3] + bv[na].y);
                *(float2*)(o1 + col) = v;
            }
        }
    }
}

// ============================================================================
// Launch
// ============================================================================
extern "C" void kernel_launch(void* const* d_in, const int* in_sizes, int n_in,
                              void* d_out, int out_size) {
    const float* x       = (const float*)d_in[0];
    const void*  sid     = (const void*)d_in[1];
    const float* W       = (const float*)d_in[2];
    const float* bias    = (const float*)d_in[3];
    float* out           = (float*)d_out;

    cudaFuncSetAttribute(k_gemm, cudaFuncAttributeMaxDynamicSharedMemorySize, SMEM_TOTAL);

    k_detect<<<1, 128>>>((const int*)sid);
    k_init<<<40, 256>>>();
    k_hist<<<BB / 256, 256>>>(sid);
    k_plan<<<1, 1>>>();
    k_scatter<<<BB / 256, 256>>>(sid);

    dim3 gg(MAX_TILES, NT_N);
    k_gemm<<<gg, NTHREADS, SMEM_TOTAL>>>(x, W, bias, out);
}

// round 4
// speedup vs baseline: 1.1958x; 1.1958x over previous
#include <cuda_runtime.h>
#include <cstdint>

// ============================================================================
// Problem constants
// ============================================================================
static constexpr int BB   = 8192;   // batch
static constexpr int IN_  = 2048;   // K
static constexpr int OUT_ = 3072;   // N total
static constexpr int S_   = 8;      // subjects

static constexpr int TM   = 128;    // CTA M tile
static constexpr int TN   = 256;    // CTA N tile
static constexpr int KC   = 32;     // K per chunk
static constexpr int NKC  = IN_ / KC;    // 64
static constexpr int NT_N = OUT_ / TN;   // 12
static constexpr int MAX_TILES = 72;     // >= 8192/128 + 7 pad tiles
static constexpr int NTHREADS = 256;     // 8 warps: 2 (m) x 4 (n), warp tile 64x64
static constexpr int STAGES = 4;

static constexpr int A_BYTES = TM * KC * 4;           // 16384
static constexpr int B_BYTES = KC * TN * 4;           // 32768
static constexpr int STAGE_BYTES = A_BYTES + B_BYTES; // 49152
static constexpr int SMEM_TOTAL  = STAGES * STAGE_BYTES; // 196608

// ============================================================================
// Device globals (scratch)
// ============================================================================
__device__ int g_is64;
__device__ int g_counts[S_];
__device__ int g_cursor[S_];
__device__ int g_pad_off[S_];
__device__ int g_tile_subject[MAX_TILES];
__device__ int g_perm[MAX_TILES * TM];
__device__ float g_xp[(size_t)MAX_TILES * TM * IN_];   // gathered + tf32-rounded x

// ============================================================================
// Helpers
// ============================================================================
#define DI __device__ __forceinline__

DI unsigned smem_u32(const void* p) {
    unsigned a;
    asm("{ .reg .u64 t; cvta.to.shared.u64 t, %1; cvt.u32.u64 %0, t; }" : "=r"(a) : "l"(p));
    return a;
}
// A tile: 128 rows (m) x 128B (k). xor bits[6:4] with row%8
DI unsigned swzA(unsigned o) { return o ^ ((o >> 3) & 0x70u); }
// B tile: 32 rows (k) x 1024B (n). xor bits[6:5] with k%4
DI unsigned swzB(unsigned o) { return o ^ ((o >> 5) & 0x60u); }

DI void cpasync16(unsigned dst, const void* src) {
    asm volatile("cp.async.cg.shared.global [%0], [%1], 16;"
                 :: "r"(dst), "l"(src) : "memory");
}
DI void cp_commit() { asm volatile("cp.async.commit_group;" ::: "memory"); }
template <int N> DI void cp_wait() {
    asm volatile("cp.async.wait_group %0;" :: "n"(N) : "memory");
}
DI unsigned lds32(unsigned addr) {
    unsigned v;
    asm volatile("ld.shared.b32 %0, [%1];" : "=r"(v) : "r"(addr));
    return v;
}
DI void ldm4(unsigned* r, unsigned addr) {
    asm volatile("ldmatrix.sync.aligned.m8n8.x4.shared.b16 {%0,%1,%2,%3}, [%4];"
                 : "=r"(r[0]), "=r"(r[1]), "=r"(r[2]), "=r"(r[3]) : "r"(addr));
}
DI void mma_tf32(float* d, const unsigned* a, const unsigned* b) {
    asm volatile(
        "mma.sync.aligned.m16n8k8.row.col.f32.tf32.tf32.f32 "
        "{%0,%1,%2,%3}, {%4,%5,%6,%7}, {%8,%9}, {%0,%1,%2,%3};"
        : "+f"(d[0]), "+f"(d[1]), "+f"(d[2]), "+f"(d[3])
        : "r"(a[0]), "r"(a[1]), "r"(a[2]), "r"(a[3]), "r"(b[0]), "r"(b[1]));
}
DI float rna_tf32(float v) {
    unsigned u;
    asm("cvt.rna.tf32.f32 %0, %1;" : "=r"(u) : "f"(v));
    return __uint_as_float(u);
}
DI int read_sid(const void* sid, int b) {
    if (g_is64) return (int)((const long long*)sid)[b];
    return ((const int*)sid)[b];
}

// ============================================================================
// Setup kernels
// ============================================================================
// init + dtype-detect (int64 small values => every odd int32 word is zero)
__global__ void k_init(const int* __restrict__ sid_raw) {
    int t = blockIdx.x * blockDim.x + threadIdx.x;
    if (blockIdx.x == 0) {
        __shared__ int nz;
        if (threadIdx.x == 0) nz = 0;
        __syncthreads();
        int j = 2 * threadIdx.x + 1;
        if (threadIdx.x < 128 && sid_raw[j] != 0) atomicOr(&nz, 1);
        __syncthreads();
        if (threadIdx.x == 0) g_is64 = (nz == 0) ? 1 : 0;
    }
    if (t < S_) { g_counts[t] = 0; g_cursor[t] = 0; }
    if (t < MAX_TILES) g_tile_subject[t] = -1;
    for (int i = t; i < MAX_TILES * TM; i += gridDim.x * blockDim.x) g_perm[i] = -1;
}
__global__ void k_hist(const void* __restrict__ sid) {
    __shared__ int lc[S_];
    int t = threadIdx.x;
    int b = blockIdx.x * blockDim.x + t;
    if (t < S_) lc[t] = 0;
    __syncthreads();
    atomicAdd(&lc[read_sid(sid, b) & (S_ - 1)], 1);
    __syncthreads();
    if (t < S_ && lc[t] > 0) atomicAdd(&g_counts[t], lc[t]);
}
__global__ void k_plan() {
    int off = 0, tile = 0;
    for (int s = 0; s < S_; s++) {
        g_pad_off[s] = off;
        int nt = (g_counts[s] + TM - 1) / TM;
        for (int t = 0; t < nt; t++) g_tile_subject[tile++] = s;
        off += nt * TM;
    }
}
__global__ void k_scatter(const void* __restrict__ sid) {
    __shared__ int lc[S_], lbase[S_];
    int t = threadIdx.x;
    int b = blockIdx.x * blockDim.x + t;
    if (t < S_) lc[t] = 0;
    __syncthreads();
    int s = read_sid(sid, b) & (S_ - 1);
    int r = atomicAdd(&lc[s], 1);
    __syncthreads();
    if (t < S_) lbase[t] = (lc[t] > 0) ? atomicAdd(&g_cursor[t], lc[t]) : 0;
    __syncthreads();
    g_perm[g_pad_off[s] + lbase[s] + r] = b;
}
// gather + RNA-round x into padded tile order; padding rows -> 0
__global__ void k_prep(const float* __restrict__ x) {
    const int rp = blockIdx.x;
    const int p  = g_perm[rp];
    float4* dst = (float4*)(g_xp + (size_t)rp * IN_);
    if (p < 0) {
        for (int i = threadIdx.x; i < IN_ / 4; i += blockDim.x)
            dst[i] = make_float4(0.f, 0.f, 0.f, 0.f);
        return;
    }
    const float4* src = (const float4*)(x + (size_t)p * IN_);
    for (int i = threadIdx.x; i < IN_ / 4; i += blockDim.x) {
        float4 v = src[i];
        v.x = rna_tf32(v.x); v.y = rna_tf32(v.y);
        v.z = rna_tf32(v.z); v.w = rna_tf32(v.w);
        dst[i] = v;
    }
}

// ============================================================================
// Grouped tf32 GEMM. CTA: 128(m) x 256(n), 8 warps (2m x 4n), warp 64x64.
// A from g_xp (pre-rounded) via ldmatrix.x4; B from W (implicit truncation)
// via scalar LDS. 4-stage cp.async pipeline, K chunks of 32.
// ============================================================================
__global__ void __launch_bounds__(NTHREADS, 1)
k_gemm(const float* __restrict__ W, const float* __restrict__ bias,
       float* __restrict__ out) {
    extern __shared__ char smem[];
    const int sub = g_tile_subject[blockIdx.x];
    if (sub < 0) return;

    const int tid  = threadIdx.x;
    const int wid  = tid >> 5;
    const int lane = tid & 31;
    const int q    = lane >> 2;    // 0..7
    const int kk   = lane & 3;     // 0..3
    const int wm   = wid >> 2;     // 0..1
    const int wn   = wid & 3;      // 0..3
    const int m_base = blockIdx.x * TM;
    const int n_base = blockIdx.y * TN;
    const unsigned sb = smem_u32(smem);

    const float* Ws = W + (size_t)sub * IN_ * OUT_;
    const float* xp = g_xp + (size_t)m_base * IN_;

    // ---- cp.async address precompute ----
    // A: 1024 float4 per chunk, 4 per thread
    unsigned adst_[4]; int aoff_[4];
#pragma unroll
    for (int i = 0; i < 4; i++) {
        int idx = i * NTHREADS + tid;
        int row = idx >> 3, f4 = idx & 7;
        adst_[i] = swzA((unsigned)(row * 128 + f4 * 16));
        aoff_[i] = row * IN_ + f4 * 4;
    }
    // B: 2048 float4 per chunk, 8 per thread
    unsigned bdst_[8]; int boff_[8];
#pragma unroll
    for (int i = 0; i < 8; i++) {
        int idx = i * NTHREADS + tid;
        int krow = idx >> 6, nf4 = idx & 63;
        bdst_[i] = swzB((unsigned)(krow * 1024 + nf4 * 16));
        boff_[i] = krow * OUT_ + nf4 * 4;
    }

    // ---- pipeline prologue: chunks 0..2 ----
#pragma unroll
    for (int c = 0; c < STAGES - 1; c++) {
        const unsigned st = sb + (unsigned)c * STAGE_BYTES;
        const float* as = xp + c * KC;
        const float* bs = Ws + (size_t)(c * KC) * OUT_ + n_base;
#pragma unroll
        for (int i = 0; i < 4; i++) cpasync16(st + adst_[i], as + aoff_[i]);
#pragma unroll
        for (int i = 0; i < 8; i++) cpasync16(st + A_BYTES + bdst_[i], bs + boff_[i]);
        cp_commit();
    }

    float acc[4][8][4];
#pragma unroll
    for (int i = 0; i < 4; i++)
#pragma unroll
        for (int j = 0; j < 8; j++)
#pragma unroll
            for (int c = 0; c < 4; c++) acc[i][j][c] = 0.f;

    // ---- ldmatrix lane geometry for A ----
    // lane l: tile t = l/8, row-in-tile r = l%8
    // tile 0: rows +0..7 bytes +0 ; tile 1: rows +8..15 bytes +0
    // tile 2: rows +0..7 bytes +16; tile 3: rows +8..15 bytes +16
    const int lt = lane >> 3, lr = lane & 7;
    const int arow_f = ((lt & 1) << 3) + lr;           // row within 16-row block
    const unsigned acol_f = (unsigned)((lt >> 1) << 4);// 0 or 16
    const unsigned axor = (unsigned)(lr << 4);         // swizzle xor (row%8)*16
    // B column base: ((wn*64 + na*8 + q)*4) ^ (kk*32) = bbase + ((na^kk)<<5)
    const unsigned bbase = (unsigned)(wn * 256 + q * 4);

    // ---- main loop ----
#pragma unroll 1
    for (int kc = 0; kc < NKC; kc++) {
        cp_wait<STAGES - 2>();
        __syncthreads();
        const unsigned st = sb + (unsigned)(kc % STAGES) * STAGE_BYTES;
        const unsigned aT = st;
        const unsigned bT = st + A_BYTES;

#pragma unroll
        for (int ks = 0; ks < 4; ks++) {
            const unsigned aco = ((unsigned)(ks * 32) + acol_f) ^ axor;
            unsigned a[4][4];
#pragma unroll
            for (int ma = 0; ma < 4; ma++)
                ldm4(a[ma], aT + (unsigned)((wm * 64 + ma * 16 + arow_f) * 128) + aco);

            const unsigned brow0 = bT + (unsigned)((ks * 8 + kk) * 1024);
            unsigned b[8][2];
#pragma unroll
            for (int na = 0; na < 8; na++) {
                const unsigned co = bbase + (unsigned)(((na ^ kk) & 7) << 5);
                b[na][0] = lds32(brow0 + co);
                b[na][1] = lds32(brow0 + 4096 + co);
            }
#pragma unroll
            for (int ma = 0; ma < 4; ma++)
#pragma unroll
                for (int na = 0; na < 8; na++)
                    mma_tf32(acc[ma][na], a[ma], b[na]);
        }

        // prefetch chunk kc+3
        const int nk = kc + STAGES - 1;
        if (nk < NKC) {
            const unsigned ns = sb + (unsigned)(nk % STAGES) * STAGE_BYTES;
            const float* as = xp + nk * KC;
            const float* bs = Ws + (size_t)(nk * KC) * OUT_ + n_base;
#pragma unroll
            for (int i = 0; i < 4; i++) cpasync16(ns + adst_[i], as + aoff_[i]);
#pragma unroll
            for (int i = 0; i < 8; i++) cpasync16(ns + A_BYTES + bdst_[i], bs + boff_[i]);
        }
        cp_commit();
    }

    // ---- epilogue: scatter rows through g_perm, add bias ----
    const float* bias_s = bias + (size_t)sub * OUT_;
    float2 bv[8];
#pragma unroll
    for (int na = 0; na < 8; na++) {
        const int col = n_base + wn * 64 + na * 8 + kk * 2;
        bv[na] = *(const float2*)(bias_s + col);
    }
#pragma unroll
    for (int ma = 0; ma < 4; ma++) {
        const int mr = m_base + wm * 64 + ma * 16 + q;
        const int p0 = g_perm[mr];
        const int p1 = g_perm[mr + 8];
        float* o0 = out + (size_t)(p0 < 0 ? 0 : p0) * OUT_;
        float* o1 = out + (size_t)(p1 < 0 ? 0 : p1) * OUT_;
#pragma unroll
        for (int na = 0; na < 8; na++) {
            const int col = n_base + wn * 64 + na * 8 + kk * 2;
            if (p0 >= 0) {
                float2 v = make_float2(acc[ma][na][0] + bv[na].x,
                                       acc[ma][na][1] + bv[na].y);
                *(float2*)(o0 + col) = v;
            }
            if (p1 >= 0) {
                float2 v = make_float2(acc[ma][na][2] + bv[na].x,
                                       acc[ma][na][3] + bv[na].y);
                *(float2*)(o1 + col) = v;
            }
        }
    }
}

// ============================================================================
// Launch
// ============================================================================
extern "C" void kernel_launch(void* const* d_in, const int* in_sizes, int n_in,
                              void* d_out, int out_size) {
    const float* x       = (const float*)d_in[0];
    const void*  sid     = (const void*)d_in[1];
    const float* W       = (const float*)d_in[2];
    const float* bias    = (const float*)d_in[3];
    float* out           = (float*)d_out;

    cudaFuncSetAttribute(k_gemm, cudaFuncAttributeMaxDynamicSharedMemorySize, SMEM_TOTAL);

    k_init<<<40, 256>>>((const int*)sid);       // launch 1
    k_hist<<<BB / 256, 256>>>(sid);             // launch 2
    k_plan<<<1, 1>>>();                         // launch 3
    k_scatter<<<BB / 256, 256>>>(sid);          // launch 4
    k_prep<<<MAX_TILES * TM, 256>>>(x);         // launch 5
    dim3 gg(MAX_TILES, NT_N);
    k_gemm<<<gg, NTHREADS, SMEM_TOTAL>>>(W, bias, out);  // launch 6 (ncu -s 5)
}

// round 5
// speedup vs baseline: 1.2153x; 1.0163x over previous
#include <cuda_runtime.h>
#include <cstdint>

// ============================================================================
// Problem constants
// ============================================================================
static constexpr int BB   = 8192;   // batch
static constexpr int IN_  = 2048;   // K
static constexpr int OUT_ = 3072;   // N total
static constexpr int S_   = 8;      // subjects

static constexpr int TM   = 128;    // CTA M tile
static constexpr int TN   = 256;    // CTA N tile
static constexpr int CHUNK = 64;    // K per chunk (two 32-halves)
static constexpr int NCHUNK = IN_ / CHUNK;  // 32
static constexpr int NT_N = OUT_ / TN;      // 12
static constexpr int MAX_TILES = 72;
static constexpr int NTHREADS = 256;        // 8 warps: 2(m) x 4(n), warp 64x64

static constexpr int A_HALF = TM * 32 * 4;   // 16384
static constexpr int B_HALF = 32 * TN * 4;   // 32768
static constexpr int STAGE_BYTES = 2 * A_HALF + 2 * B_HALF;  // 98304
static constexpr int SMEM_TOTAL  = 2 * STAGE_BYTES;          // 196608
// stage layout: [A0 @0][A1 @16384][B0 @32768][B1 @65536]

// ============================================================================
// Device globals (scratch)
// ============================================================================
__device__ int g_tile_subject[MAX_TILES];
__device__ int g_perm[MAX_TILES * TM];
__device__ float g_xp[(size_t)MAX_TILES * TM * IN_];  // gathered + tf32-rounded x

// ============================================================================
// Helpers
// ============================================================================
#define DI __device__ __forceinline__

DI unsigned smem_u32(const void* p) {
    unsigned a;
    asm("{ .reg .u64 t; cvta.to.shared.u64 t, %1; cvt.u32.u64 %0, t; }" : "=r"(a) : "l"(p));
    return a;
}
DI unsigned swzA(unsigned o) { return o ^ ((o >> 3) & 0x70u); }  // 128B rows
DI unsigned swzB(unsigned o) { return o ^ ((o >> 5) & 0x60u); }  // 1024B rows

DI void cpasync16(unsigned dst, const void* src) {
    asm volatile("cp.async.cg.shared.global [%0], [%1], 16;"
                 :: "r"(dst), "l"(src) : "memory");
}
DI void cp_commit() { asm volatile("cp.async.commit_group;" ::: "memory"); }
template <int N> DI void cp_wait() {
    asm volatile("cp.async.wait_group %0;" :: "n"(N) : "memory");
}
DI unsigned lds32(unsigned addr) {
    unsigned v;
    asm volatile("ld.shared.b32 %0, [%1];" : "=r"(v) : "r"(addr));
    return v;
}
DI void ldm4(unsigned* r, unsigned addr) {
    asm volatile("ldmatrix.sync.aligned.m8n8.x4.shared.b16 {%0,%1,%2,%3}, [%4];"
                 : "=r"(r[0]), "=r"(r[1]), "=r"(r[2]), "=r"(r[3]) : "r"(addr));
}
DI void mma_tf32(float* d, const unsigned* a, const unsigned* b) {
    asm volatile(
        "mma.sync.aligned.m16n8k8.row.col.f32.tf32.tf32.f32 "
        "{%0,%1,%2,%3}, {%4,%5,%6,%7}, {%8,%9}, {%0,%1,%2,%3};"
        : "+f"(d[0]), "+f"(d[1]), "+f"(d[2]), "+f"(d[3])
        : "r"(a[0]), "r"(a[1]), "r"(a[2]), "r"(a[3]), "r"(b[0]), "r"(b[1]));
}
DI float rna_tf32(float v) {
    unsigned u;
    asm("cvt.rna.tf32.f32 %0, %1;" : "=r"(u) : "f"(v));
    return __uint_as_float(u);
}

// ============================================================================
// Setup: single block does detect + init + hist + plan + scatter
// ============================================================================
__global__ void k_setup(const int* __restrict__ sid_raw) {
    __shared__ int nz, counts_s[S_], cursor_s[S_], pad_s[S_];
    const int tid = threadIdx.x;                 // 1024 threads
    if (tid == 0) nz = 0;
    if (tid < S_) { counts_s[tid] = 0; cursor_s[tid] = 0; }
    for (int i = tid; i < MAX_TILES * TM; i += 1024) g_perm[i] = -1;
    if (tid < MAX_TILES) g_tile_subject[tid] = -1;
    __syncthreads();
    // dtype detect: int64 small values => odd int32 words all zero
    if (tid < 128 && sid_raw[2 * tid + 1] != 0) atomicOr(&nz, 1);
    __syncthreads();
    const int is64 = (nz == 0);
    // histogram
    int svals[8];
#pragma unroll
    for (int j = 0; j < 8; j++) {
        const int b = tid + j * 1024;
        int s;
        if (is64) s = (int)((const long long*)sid_raw)[b];
        else      s = sid_raw[b];
        s &= (S_ - 1);
        svals[j] = s;
        atomicAdd(&counts_s[s], 1);
    }
    __syncthreads();
    // plan
    if (tid == 0) {
        int off = 0, tile = 0;
        for (int s = 0; s < S_; s++) {
            pad_s[s] = off;
            const int nt = (counts_s[s] + TM - 1) / TM;
            for (int t = 0; t < nt; t++) g_tile_subject[tile++] = s;
            off += nt * TM;
        }
    }
    __syncthreads();
    // scatter
#pragma unroll
    for (int j = 0; j < 8; j++) {
        const int b = tid + j * 1024;
        const int s = svals[j];
        const int r = atomicAdd(&cursor_s[s], 1);
        g_perm[pad_s[s] + r] = b;
    }
}

// gather + RNA-round x into padded tile order; padding rows -> 0
__global__ void k_prep(const float* __restrict__ x) {
    const int rp = blockIdx.x;
    const int p  = g_perm[rp];
    float4* dst = (float4*)(g_xp + (size_t)rp * IN_);
    if (p < 0) {
        for (int i = threadIdx.x; i < IN_ / 4; i += blockDim.x)
            dst[i] = make_float4(0.f, 0.f, 0.f, 0.f);
        return;
    }
    const float4* src = (const float4*)(x + (size_t)p * IN_);
    for (int i = threadIdx.x; i < IN_ / 4; i += blockDim.x) {
        float4 v = src[i];
        v.x = rna_tf32(v.x); v.y = rna_tf32(v.y);
        v.z = rna_tf32(v.z); v.w = rna_tf32(v.w);
        dst[i] = v;
    }
}

// no-op spacer so k_gemm lands on the ncu capture slot (my-launch #4)
__global__ void k_slot() {}

// ============================================================================
// Grouped tf32 GEMM. CTA 128x256, 8 warps (2m x 4n), warp 64x64.
// 2-stage pipeline of K=64 chunks; fragment double-buffer across 8 sub-steps.
// ============================================================================
#define LOADG(G, BUF, ST)                                                          \
    do {                                                                           \
        const int _kh = (G) >> 2, _ks = (G) & 3;                                   \
        const unsigned _aT = (ST) + ((unsigned)_kh << 14);                         \
        const unsigned _bT = (ST) + 0x8000u + ((unsigned)_kh << 15);               \
        const unsigned _aco = ((unsigned)(_ks * 32) + acol_f) ^ axor;              \
        _Pragma("unroll")                                                          \
        for (int _ma = 0; _ma < 4; _ma++)                                          \
            ldm4(afr[BUF][_ma],                                                    \
                 _aT + (unsigned)((wm * 64 + _ma * 16 + arow_f) * 128) + _aco);    \
        const unsigned _br0 = _bT + (unsigned)((_ks * 8 + kk) * 1024);             \
        _Pragma("unroll")                                                          \
        for (int _na = 0; _na < 8; _na++) {                                        \
            const unsigned _co = bbase + (unsigned)(((_na ^ kk) & 7) << 5);        \
            bfr[BUF][_na][0] = lds32(_br0 + _co);                                  \
            bfr[BUF][_na][1] = lds32(_br0 + 4096 + _co);                           \
        }                                                                          \
    } while (0)

__global__ void __launch_bounds__(NTHREADS, 1)
k_gemm(const float* __restrict__ W, const float* __restrict__ bias,
       float* __restrict__ out) {
    extern __shared__ char smem[];
    const int sub = g_tile_subject[blockIdx.x];
    if (sub < 0) return;

    const int tid  = threadIdx.x;
    const int wid  = tid >> 5;
    const int lane = tid & 31;
    const int q    = lane >> 2;
    const int kk   = lane & 3;
    const int wm   = wid >> 2;   // 0..1
    const int wn   = wid & 3;    // 0..3
    const int m_base = blockIdx.x * TM;
    const int n_base = blockIdx.y * TN;
    const unsigned sb = smem_u32(smem);

    const float* Ws = W + (size_t)sub * IN_ * OUT_;
    const float* xp = g_xp + (size_t)m_base * IN_;

    // ---- cp.async address precompute (per 32-wide half) ----
    unsigned adst_[4]; int aoff_[4];
#pragma unroll
    for (int i = 0; i < 4; i++) {
        const int idx = i * NTHREADS + tid;
        const int row = idx >> 3, f4 = idx & 7;
        adst_[i] = swzA((unsigned)(row * 128 + f4 * 16));
        aoff_[i] = row * IN_ + f4 * 4;
    }
    unsigned bdst_[8]; int boff_[8];
#pragma unroll
    for (int i = 0; i < 8; i++) {
        const int idx = i * NTHREADS + tid;
        const int krow = idx >> 6, nf4 = idx & 63;
        bdst_[i] = swzB((unsigned)(krow * 1024 + nf4 * 16));
        boff_[i] = krow * OUT_ + nf4 * 4;
    }

    // issue one full K=64 chunk (both halves) into stage st
#define ISSUE_CHUNK(ST, KOFF)                                                      \
    do {                                                                           \
        const float* _as = xp + (KOFF);                                            \
        const float* _bs = Ws + (size_t)(KOFF) * OUT_ + n_base;                    \
        _Pragma("unroll")                                                          \
        for (int _i = 0; _i < 4; _i++) {                                           \
            cpasync16((ST) + adst_[_i], _as + aoff_[_i]);                          \
            cpasync16((ST) + 16384u + adst_[_i], _as + aoff_[_i] + 32);            \
        }                                                                          \
        _Pragma("unroll")                                                          \
        for (int _i = 0; _i < 8; _i++) {                                           \
            cpasync16((ST) + 0x8000u + bdst_[_i], _bs + boff_[_i]);                \
            cpasync16((ST) + 0x8000u + 0x8000u + bdst_[_i],                        \
                      _bs + boff_[_i] + (size_t)32 * OUT_);                        \
        }                                                                          \
    } while (0)

    // ---- prologue: chunk 0 -> stage 0 ----
    ISSUE_CHUNK(sb, 0);
    cp_commit();

    float acc[4][8][4];
#pragma unroll
    for (int i = 0; i < 4; i++)
#pragma unroll
        for (int j = 0; j < 8; j++)
#pragma unroll
            for (int c = 0; c < 4; c++) acc[i][j][c] = 0.f;

    // ldmatrix lane geometry for A (same as R4)
    const int lt = lane >> 3, lr = lane & 7;
    const int arow_f = ((lt & 1) << 3) + lr;
    const unsigned acol_f = (unsigned)((lt >> 1) << 4);
    const unsigned axor = (unsigned)(lr << 4);
    const unsigned bbase = (unsigned)(wn * 256 + q * 4);

    unsigned afr[2][4][4], bfr[2][8][2];

    // ---- main loop over K=64 chunks, 2-stage ----
#pragma unroll 1
    for (int kc = 0; kc < NCHUNK; kc++) {
        cp_wait<0>();
        __syncthreads();
        const unsigned st = sb + (unsigned)(kc & 1) * STAGE_BYTES;

        LOADG(0, 0, st);                     // prime fragment pipeline
        if (kc + 1 < NCHUNK) {               // prefetch next chunk
            const unsigned ns = sb + (unsigned)((kc + 1) & 1) * STAGE_BYTES;
            ISSUE_CHUNK(ns, (kc + 1) * CHUNK);
        }
        cp_commit();

#pragma unroll
        for (int g = 0; g < 8; g++) {
            if (g < 7) LOADG(g + 1, (g + 1) & 1, st);
            const int cb = g & 1;
#pragma unroll
            for (int ma = 0; ma < 4; ma++)
#pragma unroll
                for (int na = 0; na < 8; na++)
                    mma_tf32(acc[ma][na], afr[cb][ma], bfr[cb][na]);
        }
    }

    // ---- epilogue: scatter rows through g_perm, add bias ----
    const float* bias_s = bias + (size_t)sub * OUT_;
    float2 bv[8];
#pragma unroll
    for (int na = 0; na < 8; na++) {
        const int col = n_base + wn * 64 + na * 8 + kk * 2;
        bv[na] = *(const float2*)(bias_s + col);
    }
#pragma unroll
    for (int ma = 0; ma < 4; ma++) {
        const int mr = m_base + wm * 64 + ma * 16 + q;
        const int p0 = g_perm[mr];
        const int p1 = g_perm[mr + 8];
        float* o0 = out + (size_t)(p0 < 0 ? 0 : p0) * OUT_;
        float* o1 = out + (size_t)(p1 < 0 ? 0 : p1) * OUT_;
#pragma unroll
        for (int na = 0; na < 8; na++) {
            const int col = n_base + wn * 64 + na * 8 + kk * 2;
            if (p0 >= 0) {
                float2 v = make_float2(acc[ma][na][0] + bv[na].x,
                                       acc[ma][na][1] + bv[na].y);
                *(float2*)(o0 + col) = v;
            }
            if (p1 >= 0) {
                float2 v = make_float2(acc[ma][na][2] + bv[na].x,
                                       acc[ma][na][3] + bv[na].y);
                *(float2*)(o1 + col) = v;
            }
        }
    }
}

// ============================================================================
// Launch
// ============================================================================
extern "C" void kernel_launch(void* const* d_in, const int* in_sizes, int n_in,
                              void* d_out, int out_size) {
    const float* x    = (const float*)d_in[0];
    const void*  sid  = (const void*)d_in[1];
    const float* W    = (const float*)d_in[2];
    const float* bias = (const float*)d_in[3];
    float* out        = (float*)d_out;

    cudaFuncSetAttribute(k_gemm, cudaFuncAttributeMaxDynamicSharedMemorySize, SMEM_TOTAL);

    k_setup<<<1, 1024>>>((const int*)sid);        // launch 1
    k_prep<<<MAX_TILES * TM, 256>>>(x);           // launch 2
    k_slot<<<1, 32>>>();                          // launch 3 (spacer)
    dim3 gg(MAX_TILES, NT_N);
    k_gemm<<<gg, NTHREADS, SMEM_TOTAL>>>(W, bias, out);  // launch 4 <- ncu slot
}

// round 6
// speedup vs baseline: 1.4059x; 1.1568x over previous
#include <cuda_runtime.h>
#include <cstdint>

// ============================================================================
// Problem constants
// ============================================================================
static constexpr int BB   = 8192;
static constexpr int IN_  = 2048;
static constexpr int OUT_ = 3072;
static constexpr int S_   = 8;

static constexpr int TM   = 128;
static constexpr int TN   = 256;
static constexpr int KC   = 32;            // K per chunk
static constexpr int NKC  = IN_ / KC;      // 64
static constexpr int NT_N = OUT_ / TN;     // 12
static constexpr int MAX_TILES = 72;
static constexpr int NTHREADS = 256;       // 8 warps: 2(m) x 4(n), warp 64x64
static constexpr int STAGES = 4;

static constexpr int A_BYTES = TM * KC * 4;            // 16384
static constexpr int B_BYTES = KC * TN * 4;            // 32768
static constexpr int STAGE_BYTES = A_BYTES + B_BYTES;  // 49152
static constexpr int SMEM_TOTAL  = STAGES * STAGE_BYTES; // 196608

// ============================================================================
// Device globals
// ============================================================================
__device__ int g_tile_subject[MAX_TILES];
__device__ int g_perm[MAX_TILES * TM];
__device__ float g_xp[(size_t)MAX_TILES * TM * IN_];  // gathered, tf32-rounded x

// ============================================================================
// Helpers
// ============================================================================
#define DI __device__ __forceinline__

DI unsigned smem_u32(const void* p) {
    unsigned a;
    asm("{ .reg .u64 t; cvta.to.shared.u64 t, %1; cvt.u32.u64 %0, t; }" : "=r"(a) : "l"(p));
    return a;
}
DI unsigned swzA(unsigned o) { return o ^ ((o >> 3) & 0x70u); }
DI unsigned swzB(unsigned o) { return o ^ ((o >> 5) & 0x60u); }

DI void cpasync16(unsigned dst, const void* src) {
    asm volatile("cp.async.cg.shared.global [%0], [%1], 16;"
                 :: "r"(dst), "l"(src) : "memory");
}
DI void cp_commit() { asm volatile("cp.async.commit_group;" ::: "memory"); }
template <int N> DI void cp_wait() {
    asm volatile("cp.async.wait_group %0;" :: "n"(N) : "memory");
}
DI unsigned lds32(unsigned addr) {
    unsigned v;
    asm volatile("ld.shared.b32 %0, [%1];" : "=r"(v) : "r"(addr));
    return v;
}
DI void ldm4(unsigned* r, unsigned addr) {
    asm volatile("ldmatrix.sync.aligned.m8n8.x4.shared.b16 {%0,%1,%2,%3}, [%4];"
                 : "=r"(r[0]), "=r"(r[1]), "=r"(r[2]), "=r"(r[3]) : "r"(addr));
}
DI void mma_tf32(float* d, const unsigned* a, const unsigned* b) {
    asm volatile(
        "mma.sync.aligned.m16n8k8.row.col.f32.tf32.tf32.f32 "
        "{%0,%1,%2,%3}, {%4,%5,%6,%7}, {%8,%9}, {%0,%1,%2,%3};"
        : "+f"(d[0]), "+f"(d[1]), "+f"(d[2]), "+f"(d[3])
        : "r"(a[0]), "r"(a[1]), "r"(a[2]), "r"(a[3]), "r"(b[0]), "r"(b[1]));
}
DI float rna_tf32(float v) {
    unsigned u;
    asm("cvt.rna.tf32.f32 %0, %1;" : "=r"(u) : "f"(v));
    return __uint_as_float(u);
}

// ============================================================================
// Setup: single block — detect + init + hist + plan + scatter
// ============================================================================
__global__ void k_setup(const int* __restrict__ sid_raw) {
    __shared__ int nz, counts_s[S_], cursor_s[S_], pad_s[S_];
    const int tid = threadIdx.x;  // 1024
    if (tid == 0) nz = 0;
    if (tid < S_) { counts_s[tid] = 0; cursor_s[tid] = 0; }
    for (int i = tid; i < MAX_TILES * TM; i += 1024) g_perm[i] = -1;
    if (tid < MAX_TILES) g_tile_subject[tid] = -1;
    __syncthreads();
    if (tid < 128 && sid_raw[2 * tid + 1] != 0) atomicOr(&nz, 1);
    __syncthreads();
    const int is64 = (nz == 0);
    int svals[8];
#pragma unroll
    for (int j = 0; j < 8; j++) {
        const int b = tid + j * 1024;
        int s = is64 ? (int)((const long long*)sid_raw)[b] : sid_raw[b];
        s &= (S_ - 1);
        svals[j] = s;
        atomicAdd(&counts_s[s], 1);
    }
    __syncthreads();
    if (tid == 0) {
        int off = 0, tile = 0;
        for (int s = 0; s < S_; s++) {
            pad_s[s] = off;
            const int nt = (counts_s[s] + TM - 1) / TM;
            for (int t = 0; t < nt; t++) g_tile_subject[tile++] = s;
            off += nt * TM;
        }
    }
    __syncthreads();
#pragma unroll
    for (int j = 0; j < 8; j++) {
        const int b = tid + j * 1024;
        const int s = svals[j];
        const int r = atomicAdd(&cursor_s[s], 1);
        g_perm[pad_s[s] + r] = b;
    }
}

__global__ void k_prep(const float* __restrict__ x) {
    const int rp = blockIdx.x;
    const int p  = g_perm[rp];
    float4* dst = (float4*)(g_xp + (size_t)rp * IN_);
    if (p < 0) {
        for (int i = threadIdx.x; i < IN_ / 4; i += blockDim.x)
            dst[i] = make_float4(0.f, 0.f, 0.f, 0.f);
        return;
    }
    const float4* src = (const float4*)(x + (size_t)p * IN_);
    for (int i = threadIdx.x; i < IN_ / 4; i += blockDim.x) {
        float4 v = src[i];
        v.x = rna_tf32(v.x); v.y = rna_tf32(v.y);
        v.z = rna_tf32(v.z); v.w = rna_tf32(v.w);
        dst[i] = v;
    }
}

__global__ void k_slot() {}   // spacer: k_gemm = launch 4 (ncu -s 5 slot)

// ============================================================================
// Grouped tf32 GEMM. CTA 128x256, 8 warps (2m x 4n), warp 64x64.
// 4-stage K=32 pipeline (prefetch distance 3, wait<2>), fragment
// double-buffer pipelined ACROSS chunk boundaries.
// ============================================================================

// load fragments for sub-step KS of the chunk in stage ST into buffer BUF
#define LOADG(KS, BUF, ST)                                                         \
    do {                                                                           \
        const unsigned _aco = ((unsigned)((KS) * 32) + acol_f) ^ axor;             \
        _Pragma("unroll")                                                          \
        for (int _ma = 0; _ma < 4; _ma++)                                          \
            ldm4(afr[BUF][_ma],                                                    \
                 (ST) + (unsigned)((wm * 64 + _ma * 16 + arow_f) * 128) + _aco);   \
        const unsigned _br0 = (ST) + (unsigned)A_BYTES                             \
                              + (unsigned)(((KS) * 8 + kk) * 1024);                \
        _Pragma("unroll")                                                          \
        for (int _na = 0; _na < 8; _na++) {                                        \
            const unsigned _co = bbase + (unsigned)(((_na ^ kk) & 7) << 5);        \
            bfr[BUF][_na][0] = lds32(_br0 + _co);                                  \
            bfr[BUF][_na][1] = lds32(_br0 + 4096 + _co);                           \
        }                                                                          \
    } while (0)

#define MMAALL(BUF)                                                                \
    do {                                                                           \
        _Pragma("unroll")                                                          \
        for (int _ma = 0; _ma < 4; _ma++)                                          \
            _Pragma("unroll")                                                      \
            for (int _na = 0; _na < 8; _na++)                                      \
                mma_tf32(acc[_ma][_na], afr[BUF][_ma], bfr[BUF][_na]);             \
    } while (0)

#define ISSUE_CHUNK(ST, KOFF)                                                      \
    do {                                                                           \
        const float* _as = xp + (KOFF);                                            \
        const float* _bs = Ws + (size_t)(KOFF) * OUT_ + n_base;                    \
        _Pragma("unroll")                                                          \
        for (int _i = 0; _i < 4; _i++) cpasync16((ST) + adst_[_i], _as + aoff_[_i]); \
        _Pragma("unroll")                                                          \
        for (int _i = 0; _i < 8; _i++)                                             \
            cpasync16((ST) + (unsigned)A_BYTES + bdst_[_i], _bs + boff_[_i]);      \
    } while (0)

__global__ void __launch_bounds__(NTHREADS, 1)
k_gemm(const float* __restrict__ W, const float* __restrict__ bias,
       float* __restrict__ out) {
    extern __shared__ char smem[];
    const int sub = g_tile_subject[blockIdx.x];
    if (sub < 0) return;

    const int tid  = threadIdx.x;
    const int wid  = tid >> 5;
    const int lane = tid & 31;
    const int q    = lane >> 2;
    const int kk   = lane & 3;
    const int wm   = wid >> 2;
    const int wn   = wid & 3;
    const int m_base = blockIdx.x * TM;
    const int n_base = blockIdx.y * TN;
    const unsigned sb = smem_u32(smem);

    const float* Ws = W + (size_t)sub * IN_ * OUT_;
    const float* xp = g_xp + (size_t)m_base * IN_;

    // cp.async address precompute (K=32 chunk)
    unsigned adst_[4]; int aoff_[4];
#pragma unroll
    for (int i = 0; i < 4; i++) {
        const int idx = i * NTHREADS + tid;
        const int row = idx >> 3, f4 = idx & 7;
        adst_[i] = swzA((unsigned)(row * 128 + f4 * 16));
        aoff_[i] = row * IN_ + f4 * 4;
    }
    unsigned bdst_[8]; int boff_[8];
#pragma unroll
    for (int i = 0; i < 8; i++) {
        const int idx = i * NTHREADS + tid;
        const int krow = idx >> 6, nf4 = idx & 63;
        bdst_[i] = swzB((unsigned)(krow * 1024 + nf4 * 16));
        boff_[i] = krow * OUT_ + nf4 * 4;
    }

    // prologue: chunks 0..2 into stages 0..2
#pragma unroll
    for (int c = 0; c < STAGES - 1; c++) {
        ISSUE_CHUNK(sb + (unsigned)c * STAGE_BYTES, c * KC);
        cp_commit();
    }

    float acc[4][8][4];
#pragma unroll
    for (int i = 0; i < 4; i++)
#pragma unroll
        for (int j = 0; j < 8; j++)
#pragma unroll
            for (int c = 0; c < 4; c++) acc[i][j][c] = 0.f;

    // ldmatrix lane geometry (A)
    const int lt = lane >> 3, lr = lane & 7;
    const int arow_f = ((lt & 1) << 3) + lr;
    const unsigned acol_f = (unsigned)((lt >> 1) << 4);
    const unsigned axor = (unsigned)(lr << 4);
    const unsigned bbase = (unsigned)(wn * 256 + q * 4);

    unsigned afr[2][4][4], bfr[2][8][2];

    cp_wait<2>();            // chunk 0 complete
    __syncthreads();
    LOADG(0, 0, sb);         // prime g0 of chunk 0 into buf 0

    // main loop: g0,g2 in buf0; g1,g3 in buf1; next-chunk g0 back into buf0
#pragma unroll 1
    for (int kc = 0; kc < NKC; kc++) {
        const unsigned st = sb + (unsigned)(kc & (STAGES - 1)) * STAGE_BYTES;

        LOADG(1, 1, st);                       // g0
        MMAALL(0);
        LOADG(2, 0, st);                       // g1
        MMAALL(1);
        if (kc + STAGES - 1 < NKC) {           // prefetch chunk kc+3
            const unsigned ns = sb + (unsigned)((kc + STAGES - 1) & (STAGES - 1)) * STAGE_BYTES;
            ISSUE_CHUNK(ns, (kc + STAGES - 1) * KC);
        }
        cp_commit();                           // unconditional: keeps group count exact
        LOADG(3, 1, st);                       // g2
        MMAALL(0);
        cp_wait<2>();                          // chunk kc+1 complete
        __syncthreads();                       // stage-reuse barrier
        if (kc + 1 < NKC) {                    // g0 of next chunk under final mma run
            const unsigned ns = sb + (unsigned)((kc + 1) & (STAGES - 1)) * STAGE_BYTES;
            LOADG(0, 0, ns);
        }
        MMAALL(1);                             // g3
    }

    // epilogue: scatter rows through g_perm, add bias
    const float* bias_s = bias + (size_t)sub * OUT_;
    float2 bv[8];
#pragma unroll
    for (int na = 0; na < 8; na++) {
        const int col = n_base + wn * 64 + na * 8 + kk * 2;
        bv[na] = *(const float2*)(bias_s + col);
    }
#pragma unroll
    for (int ma = 0; ma < 4; ma++) {
        const int mr = m_base + wm * 64 + ma * 16 + q;
        const int p0 = g_perm[mr];
        const int p1 = g_perm[mr + 8];
        float* o0 = out + (size_t)(p0 < 0 ? 0 : p0) * OUT_;
        float* o1 = out + (size_t)(p1 < 0 ? 0 : p1) * OUT_;
#pragma unroll
        for (int na = 0; na < 8; na++) {
            const int col = n_base + wn * 64 + na * 8 + kk * 2;
            if (p0 >= 0) {
                float2 v = make_float2(acc[ma][na][0] + bv[na].x,
                                       acc[ma][na][1] + bv[na].y);
                *(float2*)(o0 + col) = v;
            }
            if (p1 >= 0) {
                float2 v = make_float2(acc[ma][na][2] + bv[na].x,
                                       acc[ma][na][3] + bv[na].y);
                *(float2*)(o1 + col) = v;
            }
        }
    }
}

// ============================================================================
// Launch
// ============================================================================
extern "C" void kernel_launch(void* const* d_in, const int* in_sizes, int n_in,
                              void* d_out, int out_size) {
    const float* x    = (const float*)d_in[0];
    const void*  sid  = (const void*)d_in[1];
    const float* W    = (const float*)d_in[2];
    const float* bias = (const float*)d_in[3];
    float* out        = (float*)d_out;

    cudaFuncSetAttribute(k_gemm, cudaFuncAttributeMaxDynamicSharedMemorySize, SMEM_TOTAL);

    k_setup<<<1, 1024>>>((const int*)sid);               // launch 1
    k_prep<<<MAX_TILES * TM, 256>>>(x);                  // launch 2
    k_slot<<<1, 32>>>();                                 // launch 3
    dim3 gg(MAX_TILES, NT_N);
    k_gemm<<<gg, NTHREADS, SMEM_TOTAL>>>(W, bias, out);  // launch 4 <- ncu
}